// round 7
// baseline (speedup 1.0000x reference)
#include <cuda_runtime.h>
#include <math.h>

#define NN 50000
#define EE 800000
#define IN_DIM 200
#define HD 128
#define DD 127
#define GG 512
#define EPSF 1e-5f

// ---------------- scratch (device globals; no allocation allowed) ----------------
__device__ float g_h[NN * HD];      // hyperboloid buffer A
__device__ float g_hl[NN * HD];     // attention-linear hyperboloid points
__device__ float g_t1[NN * HD];     // hyperboloid buffer B (agg_combine out)
__device__ float g_t2[NN * HD];     // hyperboloid buffer C (mlp0 out)
__device__ float g_wt[6 * HD * HD];
__device__ float g_wtin[IN_DIM * HD];
__device__ int   g_cnt[NN];         // per-node degree histogram
__device__ int   g_rowptr[NN + 1];  // CSR row pointers
__device__ int   g_cur[NN];         // scatter cursors
__device__ int   g_dstidx[EE];      // CSR dst indices
__device__ int   g_blksum[256];
__device__ int   g_blkoff[256];

__device__ __forceinline__ float warp_sum(float v) {
#pragma unroll
    for (int o = 16; o; o >>= 1) v += __shfl_xor_sync(0xffffffffu, v, o);
    return v;
}

__device__ __forceinline__ void red_v4(float* p, float a, float b, float c, float d) {
    asm volatile("red.global.add.v4.f32 [%0], {%1,%2,%3,%4};"
                 :: "l"(p), "f"(a), "f"(b), "f"(c), "f"(d) : "memory");
}

// ---------------- utility kernels ----------------
__global__ void zero4_kernel(float4* __restrict__ p, int n4) {
    int i = blockIdx.x * blockDim.x + threadIdx.x;
    if (i < n4) p[i] = make_float4(0.f, 0.f, 0.f, 0.f);
}

__global__ void zeroi_kernel(int* __restrict__ p, int n) {
    int i = blockIdx.x * blockDim.x + threadIdx.x;
    if (i < n) p[i] = 0;
}

__global__ void prep_weights(const float* __restrict__ att_w, const float* __restrict__ mlp_w) {
    int idx = blockIdx.x * blockDim.x + threadIdx.x;
    if (idx >= 6 * HD * HD) return;
    int w = idx >> 14;
    int k = (idx >> 7) & 127;
    int j = idx & 127;
    float val = 0.f;
    if (k < DD && j < DD) {
        const float* src = (w < 2) ? (att_w + w * DD * DD) : (mlp_w + (w - 2) * DD * DD);
        val = src[j * DD + k];
    }
    g_wt[idx] = val;
}

__global__ void prep_win(const float* __restrict__ w_in) {
    int idx = blockIdx.x * blockDim.x + threadIdx.x;
    if (idx >= IN_DIM * HD) return;
    int k = idx >> 7;
    int j = idx & 127;
    g_wtin[idx] = (j < DD) ? w_in[k * DD + j] : 0.f;
}

// ---------------- CSR build (hist + decoupled 3-phase scan + scatter) ----------------
__global__ void hist_kernel(const int* __restrict__ ei) {
    int e = blockIdx.x * blockDim.x + threadIdx.x;
    if (e < EE) atomicAdd(&g_cnt[ei[e]], 1);
}

__global__ void scan1_kernel() {
    __shared__ int sh[256];
    int t = threadIdx.x;
    int idx = blockIdx.x * 256 + t;
    int v = (idx < NN) ? g_cnt[idx] : 0;
    sh[t] = v;
    __syncthreads();
#pragma unroll
    for (int d = 1; d < 256; d <<= 1) {
        int o = (t >= d) ? sh[t - d] : 0;
        __syncthreads();
        sh[t] += o;
        __syncthreads();
    }
    if (idx < NN) g_rowptr[idx] = sh[t] - v;
    if (t == 255) g_blksum[blockIdx.x] = sh[255];
}

__global__ void scan2_kernel(int nblk) {
    __shared__ int sh[256];
    int t = threadIdx.x;
    int v = (t < nblk) ? g_blksum[t] : 0;
    sh[t] = v;
    __syncthreads();
#pragma unroll
    for (int d = 1; d < 256; d <<= 1) {
        int o = (t >= d) ? sh[t - d] : 0;
        __syncthreads();
        sh[t] += o;
        __syncthreads();
    }
    if (t < nblk) g_blkoff[t] = sh[t] - v;
    if (t == 255) g_rowptr[NN] = sh[255];
}

__global__ void scan3_kernel() {
    int idx = blockIdx.x * 256 + threadIdx.x;
    if (idx >= NN) return;
    int r = g_rowptr[idx] + g_blkoff[blockIdx.x];
    g_rowptr[idx] = r;
    g_cur[idx] = r;
}

__global__ void scatter_kernel(const int* __restrict__ ei) {
    int e = blockIdx.x * blockDim.x + threadIdx.x;
    if (e >= EE) return;
    int s = ei[e];
    int pos = atomicAdd(&g_cur[s], 1);
    g_dstidx[pos] = ei[EE + e];
}

// ---------------- fused GEMM ----------------
// OUT[n] = Epi( bias + Pro(IN[n]) @ WT )
//   PRO 0: plain rows of IN (stride K)           — for the input GEMM (x)
//   PRO 1: logmap0 of hyperboloid IN (stride HD) — K must be 128
//   EPI 1: proj(expmap0([0, p]))                 — hyperboloid out
//   EPI 2: hyp_act: expmap0(tanh(logmap0(proj(expmap0([0,p])))))
// Key layout fact: threads with equal rg form one warp (tid = rg*32+cg), and that
// warp owns whole rows with lane cg holding cols 4cg..4cg+3 — identical to the
// standalone warp-per-node kernels, so their code applies verbatim.
template <int K, int PRO, int EPI>
__global__ void __launch_bounds__(256) gemm_fused(const float* __restrict__ IN,
                                                  const float* __restrict__ WT,
                                                  const float* __restrict__ bias,
                                                  float* __restrict__ OUT,
                                                  const float* __restrict__ cptr) {
    constexpr int TM = (K > 128) ? 56 : 64;
    constexpr int RPT = TM / 8;
    constexpr int K4 = K / 4;
    __shared__ __align__(16) float4 xs[TM * K4];
    int tid = threadIdx.x;
    int cg = tid & 31;
    int rg = tid >> 5;
    int row0 = blockIdx.x * TM;
    float c = cptr[0], sc = sqrtf(c);

    if (PRO == 0) {
        for (int i = tid; i < TM * K4; i += 256) {
            int m = i / K4, k4 = i - m * K4;
            int r = row0 + m;
            xs[i] = (r < NN) ? ((const float4*)(IN + (size_t)r * K))[k4]
                             : make_float4(0.f, 0.f, 0.f, 0.f);
        }
    } else {
        // logmap0 prologue: warp rg stages its own RPT rows (K==128, lane==cg)
#pragma unroll
        for (int r = 0; r < RPT; r++) {
            int m = rg * RPT + r;
            int gr = row0 + m;
            float4 o = make_float4(0.f, 0.f, 0.f, 0.f);
            if (gr < NN) {  // warp-uniform
                float4 v = ((const float4*)(IN + (size_t)gr * HD))[cg];
                float x0 = __shfl_sync(0xffffffffu, v.x, 0);
                float px = (cg == 0) ? 0.f : v.x * v.x;
                float s = warp_sum(px + v.y * v.y + v.z * v.z + v.w * v.w);
                float yn = fmaxf(sqrtf(s), 1e-9f);
                float d = sc * acoshf(fmaxf(x0 / sc, 1.f + EPSF));
                float a = d / yn;
                float nx = __shfl_down_sync(0xffffffffu, v.x, 1);
                o.x = a * v.y; o.y = a * v.z; o.z = a * v.w;
                o.w = (cg == 31) ? 0.f : a * nx;
            }
            xs[m * K4 + cg] = o;
        }
    }
    __syncthreads();

    float acc[RPT][4];
#pragma unroll
    for (int r = 0; r < RPT; r++) {
        acc[r][0] = 0.f; acc[r][1] = 0.f; acc[r][2] = 0.f; acc[r][3] = 0.f;
    }

    const float4* W4 = (const float4*)WT;
#pragma unroll 4
    for (int kq = 0; kq < K4; kq++) {
        float4 w0 = W4[(kq * 4 + 0) * 32 + cg];
        float4 w1 = W4[(kq * 4 + 1) * 32 + cg];
        float4 w2 = W4[(kq * 4 + 2) * 32 + cg];
        float4 w3 = W4[(kq * 4 + 3) * 32 + cg];
#pragma unroll
        for (int r = 0; r < RPT; r++) {
            float4 xv = xs[(rg * RPT + r) * K4 + kq];
            acc[r][0] = fmaf(xv.x, w0.x, acc[r][0]);
            acc[r][1] = fmaf(xv.x, w0.y, acc[r][1]);
            acc[r][2] = fmaf(xv.x, w0.z, acc[r][2]);
            acc[r][3] = fmaf(xv.x, w0.w, acc[r][3]);
            acc[r][0] = fmaf(xv.y, w1.x, acc[r][0]);
            acc[r][1] = fmaf(xv.y, w1.y, acc[r][1]);
            acc[r][2] = fmaf(xv.y, w1.z, acc[r][2]);
            acc[r][3] = fmaf(xv.y, w1.w, acc[r][3]);
            acc[r][0] = fmaf(xv.z, w2.x, acc[r][0]);
            acc[r][1] = fmaf(xv.z, w2.y, acc[r][1]);
            acc[r][2] = fmaf(xv.z, w2.z, acc[r][2]);
            acc[r][3] = fmaf(xv.z, w2.w, acc[r][3]);
            acc[r][0] = fmaf(xv.w, w3.x, acc[r][0]);
            acc[r][1] = fmaf(xv.w, w3.y, acc[r][1]);
            acc[r][2] = fmaf(xv.w, w3.z, acc[r][2]);
            acc[r][3] = fmaf(xv.w, w3.w, acc[r][3]);
        }
    }

    float4 bv = make_float4(0.f, 0.f, 0.f, 0.f);
    if (bias) {
        int j0 = 4 * cg;
        bv.x = (j0 + 0 < DD) ? bias[j0 + 0] : 0.f;
        bv.y = (j0 + 1 < DD) ? bias[j0 + 1] : 0.f;
        bv.z = (j0 + 2 < DD) ? bias[j0 + 2] : 0.f;
        bv.w = (j0 + 3 < DD) ? bias[j0 + 3] : 0.f;
    }

#pragma unroll
    for (int r = 0; r < RPT; r++) {
        int gr = row0 + rg * RPT + r;
        if (gr >= NN) continue;  // warp-uniform
        float4 v;
        v.x = acc[r][0] + bv.x;
        v.y = acc[r][1] + bv.y;
        v.z = acc[r][2] + bv.z;
        v.w = (cg == 31) ? 0.f : acc[r][3] + bv.w;  // col 127 is padding
        float4 o;
        if (EPI == 1) {
            // proj(expmap0([0, v]))  — verbatim expmap_kernel math
            float s = warp_sum(v.x * v.x + v.y * v.y + v.z * v.z + v.w * v.w);
            float n = fmaxf(sqrtf(s), 1e-9f);
            float sh = sc * sinhf(n / sc) / n;
            float wprev = __shfl_up_sync(0xffffffffu, v.w, 1);
            o.x = (cg == 0) ? 0.f : sh * wprev;
            o.y = sh * v.x; o.z = sh * v.y; o.w = sh * v.z;
            float ss = warp_sum(((cg == 0) ? 0.f : o.x * o.x) + o.y * o.y + o.z * o.z + o.w * o.w);
            if (cg == 0) o.x = sqrtf(c + ss);
        } else {
            // hyp_act(proj(expmap0([0, v])))  — verbatim mlp_epi_kernel math
            float s = warp_sum(v.x * v.x + v.y * v.y + v.z * v.z + v.w * v.w);
            float n1 = fmaxf(sqrtf(s), 1e-9f);
            float sh1 = sc * sinhf(n1 / sc) / n1;
            float sx = sh1 * v.x, sy = sh1 * v.y, sz = sh1 * v.z, sw = sh1 * v.w;
            float ssum = warp_sum(sx * sx + sy * sy + sz * sz + sw * sw);
            float x0 = sqrtf(c + ssum);
            float yn = fmaxf(sqrtf(ssum), 1e-9f);
            float d = sc * acoshf(fmaxf(x0 / sc, 1.f + EPSF));
            float cf = d / yn;
            float tx = tanhf(cf * sx), ty = tanhf(cf * sy), tz = tanhf(cf * sz), tw = tanhf(cf * sw);
            float s2 = warp_sum(tx * tx + ty * ty + tz * tz + tw * tw);
            float n2 = fmaxf(sqrtf(s2), 1e-9f);
            float sh2 = sc * sinhf(n2 / sc) / n2;
            float wprev = __shfl_up_sync(0xffffffffu, tw, 1);
            o.x = (cg == 0) ? sc * coshf(n2 / sc) : sh2 * wprev;
            o.y = sh2 * tx; o.z = sh2 * ty; o.w = sh2 * tz;
        }
        ((float4*)(OUT + (size_t)gr * HD))[cg] = o;
    }
}

// ---------------- fused agg + combine ----------------
// warp per node: centroid over CSR row (register acc, no atomics), then the full
// GIN combine, writing the new hyperboloid point to OUT (distinct buffer — no race).
__global__ void agg_combine_kernel(const float* __restrict__ hl, const float* __restrict__ h,
                                   float* __restrict__ OUT, const float* __restrict__ cptr,
                                   const float* __restrict__ epsp, int l) {
    int warp = (blockIdx.x * blockDim.x + threadIdx.x) >> 5;
    int lane = threadIdx.x & 31;
    if (warp >= NN) return;
    float c = cptr[0], sc = sqrtf(c), ep = epsp[l];
    int beg = g_rowptr[warp], end = g_rowptr[warp + 1];
    float4 a = ((const float4*)(hl + (size_t)warp * HD))[lane];
    float4 mv = make_float4(0.f, 0.f, 0.f, 0.f);
    int d = (beg < end) ? g_dstidx[beg] : 0;
    for (int e = beg; e < end; e++) {
        int dn = (e + 1 < end) ? g_dstidx[e + 1] : 0;
        float4 b = ((const float4*)(hl + (size_t)d * HD))[lane];
        float4 hv = ((const float4*)(h + (size_t)d * HD))[lane];
        float p = ((lane == 0) ? -a.x * b.x : a.x * b.x) + a.y * b.y + a.z * b.z + a.w * b.w;
        p = warp_sum(p);
        float val = fmaxf(-p / c, 1.f + EPSF);
        float att = expf(-sc * acoshf(val));
        mv.x = fmaf(att, hv.x, mv.x);
        mv.y = fmaf(att, hv.y, mv.y);
        mv.z = fmaf(att, hv.z, mv.z);
        mv.w = fmaf(att, hv.w, mv.w);
        d = dn;
    }
    // combine (verbatim combine_kernel math)
    float4 hv = ((const float4*)(h + (size_t)warp * HD))[lane];
    float m0 = __shfl_sync(0xffffffffu, mv.x, 0);
    float pm = warp_sum(((lane == 0) ? 0.f : mv.x * mv.x) + mv.y * mv.y + mv.z * mv.z + mv.w * mv.w);
    float denom = sqrtf(fmaxf(m0 * m0 - pm, 1e-9f));
    float r = sc / denom;
    float ax = r * mv.x, ay = r * mv.y, az = r * mv.z, aw = r * mv.w;
    float ssum = warp_sum(((lane == 0) ? 0.f : ax * ax) + ay * ay + az * az + aw * aw);
    float t = sqrtf(c + ssum);
    float yn_a = fmaxf(sqrtf(ssum), 1e-9f);
    float d1 = sc * acoshf(fmaxf(t / sc, 1.f + EPSF));
    float cA = d1 / yn_a;
    float ph = warp_sum(((lane == 0) ? 0.f : hv.x * hv.x) + hv.y * hv.y + hv.z * hv.z + hv.w * hv.w);
    float hp0 = sqrtf(c + ph);
    float yn_h = fmaxf(sqrtf(ph), 1e-9f);
    float d2 = sc * acoshf(fmaxf(hp0 / sc, 1.f + EPSF));
    float cH = (1.f + ep) * d2 / yn_h;
    float4 vv;
    vv.x = (lane == 0) ? 0.f : cA * ax + cH * hv.x;
    vv.y = cA * ay + cH * hv.y;
    vv.z = cA * az + cH * hv.z;
    vv.w = cA * aw + cH * hv.w;
    float pv = warp_sum(vv.x * vv.x + vv.y * vv.y + vv.z * vv.z + vv.w * vv.w);
    float n = fmaxf(sqrtf(pv), 1e-9f);
    float sh = sc * sinhf(n / sc) / n;
    float4 o;
    o.x = (lane == 0) ? 0.f : sh * vv.x;
    o.y = sh * vv.y; o.z = sh * vv.z; o.w = sh * vv.w;
    float so = warp_sum(((lane == 0) ? 0.f : o.x * o.x) + o.y * o.y + o.z * o.z + o.w * o.w);
    if (lane == 0) o.x = sqrtf(c + so);
    ((float4*)(OUT + (size_t)warp * HD))[lane] = o;
}

// pooled[batch[n], loff + i] += logmap0(h[n])[i]
__global__ void pool_kernel(const float* __restrict__ H, const int* __restrict__ batch,
                            const float* __restrict__ cptr, float* __restrict__ out, int loff) {
    int warp = (blockIdx.x * blockDim.x + threadIdx.x) >> 5;
    int lane = threadIdx.x & 31;
    if (warp >= NN) return;
    float c = cptr[0], sc = sqrtf(c);
    float4 v = ((const float4*)(H + (size_t)warp * HD))[lane];
    float x0 = __shfl_sync(0xffffffffu, v.x, 0);
    float p = warp_sum(((lane == 0) ? 0.f : v.x * v.x) + v.y * v.y + v.z * v.z + v.w * v.w);
    float yn = fmaxf(sqrtf(p), 1e-9f);
    float d = sc * acoshf(fmaxf(x0 / sc, 1.f + EPSF));
    float a = d / yn;
    int g = batch[warp];
    red_v4(out + (size_t)g * (2 * HD) + loff + lane * 4,
           (lane == 0) ? 0.f : a * v.x, a * v.y, a * v.z, a * v.w);
}

// ---------------- host launcher ----------------
extern "C" void kernel_launch(void* const* d_in, const int* in_sizes, int n_in,
                              void* d_out, int out_size) {
    (void)in_sizes; (void)n_in; (void)out_size;
    const float* x     = (const float*)d_in[0];
    const float* c     = (const float*)d_in[1];
    const float* w_in  = (const float*)d_in[2];
    const float* att_w = (const float*)d_in[3];
    const float* att_b = (const float*)d_in[4];
    const float* eps   = (const float*)d_in[5];
    const float* mlp_w = (const float*)d_in[6];
    const float* mlp_b = (const float*)d_in[7];
    const int*   ei    = (const int*)d_in[8];
    const int*   batch = (const int*)d_in[9];
    float* out = (float*)d_out;

    float *ph, *phl, *pt1, *pt2, *pwt, *pwtin;
    int* pcnt;
    cudaGetSymbolAddress((void**)&ph, g_h);
    cudaGetSymbolAddress((void**)&phl, g_hl);
    cudaGetSymbolAddress((void**)&pt1, g_t1);
    cudaGetSymbolAddress((void**)&pt2, g_t2);
    cudaGetSymbolAddress((void**)&pwt, g_wt);
    cudaGetSymbolAddress((void**)&pwtin, g_wtin);
    cudaGetSymbolAddress((void**)&pcnt, g_cnt);

    const int NB = (NN + 7) / 8;        // warp-per-node blocks (256 threads = 8 warps)
    const int GB200 = (NN + 55) / 56;   // GEMM K=200 blocks (TM=56)
    const int GB128 = (NN + 63) / 64;   // GEMM K=128 blocks (TM=64)
    const int SCB = (NN + 255) / 256;   // scan blocks (196)

    zero4_kernel<<<(GG * 2 * HD / 4 + 255) / 256, 256>>>((float4*)out, GG * 2 * HD / 4);
    prep_weights<<<(6 * HD * HD + 255) / 256, 256>>>(att_w, mlp_w);
    prep_win<<<(IN_DIM * HD + 255) / 256, 256>>>(w_in);

    // CSR build (once; reused by both layers)
    zeroi_kernel<<<SCB, 256>>>(pcnt, NN);
    hist_kernel<<<(EE + 255) / 256, 256>>>(ei);
    scan1_kernel<<<SCB, 256>>>();
    scan2_kernel<<<1, 256>>>(SCB);
    scan3_kernel<<<SCB, 256>>>();
    scatter_kernel<<<(EE + 255) / 256, 256>>>(ei);

    // input: h0 = proj(expmap0([0, x @ w_in]))
    gemm_fused<IN_DIM, 0, 1><<<GB200, 256>>>(x, pwtin, nullptr, ph, c);

    for (int l = 0; l < 2; l++) {
        // attention linear: hl = proj(expmap0(logmap0(h) @ W + b))
        gemm_fused<HD, 1, 1><<<GB128, 256>>>(ph, pwt + l * HD * HD, att_b + l * DD, phl, c);
        // centroid aggregation + GIN combine -> t1
        agg_combine_kernel<<<NB, 256>>>(phl, ph, pt1, c, eps, l);
        // MLP: t1 -> t2 -> h
        gemm_fused<HD, 1, 2><<<GB128, 256>>>(pt1, pwt + (2 + l * 2 + 0) * HD * HD,
                                             mlp_b + (l * 2 + 0) * DD, pt2, c);
        gemm_fused<HD, 1, 2><<<GB128, 256>>>(pt2, pwt + (2 + l * 2 + 1) * HD * HD,
                                             mlp_b + (l * 2 + 1) * DD, ph, c);
        // pooled readout for this layer
        pool_kernel<<<NB, 256>>>(ph, batch, c, out, l * HD);
    }
}

// round 8
// speedup vs baseline: 1.1375x; 1.1375x over previous
#include <cuda_runtime.h>
#include <math.h>

#define NN 50000
#define EE 800000
#define IN_DIM 200
#define HD 128
#define DD 127
#define GG 512
#define EPSF 1e-5f

// ---------------- scratch (device globals; no allocation allowed) ----------------
__device__ float g_h[NN * HD];      // hyperboloid node features
__device__ float g_u[NN * HD];      // logmap0 spatial (slots 0..126, slot127 = 0)
__device__ float g_p[NN * HD];      // GEMM output
__device__ float g_hl[NN * HD];     // attention-linear hyperboloid points
__device__ float g_wt[6 * HD * HD];
__device__ float g_wtin[IN_DIM * HD];
__device__ int   g_cnt[NN];
__device__ int   g_rowptr[NN + 1];
__device__ int   g_cur[NN];
__device__ int   g_dstidx[EE];
__device__ int   g_blksum[256];
__device__ int   g_blkoff[256];

__device__ __forceinline__ float warp_sum(float v) {
#pragma unroll
    for (int o = 16; o; o >>= 1) v += __shfl_xor_sync(0xffffffffu, v, o);
    return v;
}

__device__ __forceinline__ void red_v4(float* p, float a, float b, float c, float d) {
    asm volatile("red.global.add.v4.f32 [%0], {%1,%2,%3,%4};"
                 :: "l"(p), "f"(a), "f"(b), "f"(c), "f"(d) : "memory");
}

// ---------------- utility kernels ----------------
__global__ void zero4_kernel(float4* __restrict__ p, int n4) {
    int i = blockIdx.x * blockDim.x + threadIdx.x;
    if (i < n4) p[i] = make_float4(0.f, 0.f, 0.f, 0.f);
}

__global__ void zeroi_kernel(int* __restrict__ p, int n) {
    int i = blockIdx.x * blockDim.x + threadIdx.x;
    if (i < n) p[i] = 0;
}

__global__ void prep_weights(const float* __restrict__ att_w, const float* __restrict__ mlp_w) {
    int idx = blockIdx.x * blockDim.x + threadIdx.x;
    if (idx >= 6 * HD * HD) return;
    int w = idx >> 14;
    int k = (idx >> 7) & 127;
    int j = idx & 127;
    float val = 0.f;
    if (k < DD && j < DD) {
        const float* src = (w < 2) ? (att_w + w * DD * DD) : (mlp_w + (w - 2) * DD * DD);
        val = src[j * DD + k];
    }
    g_wt[idx] = val;
}

__global__ void prep_win(const float* __restrict__ w_in) {
    int idx = blockIdx.x * blockDim.x + threadIdx.x;
    if (idx >= IN_DIM * HD) return;
    int k = idx >> 7;
    int j = idx & 127;
    g_wtin[idx] = (j < DD) ? w_in[k * DD + j] : 0.f;
}

// ---------------- CSR build ----------------
__global__ void hist_kernel(const int* __restrict__ ei) {
    int e = blockIdx.x * blockDim.x + threadIdx.x;
    if (e < EE) atomicAdd(&g_cnt[ei[e]], 1);
}

__global__ void scan1_kernel() {
    __shared__ int sh[256];
    int t = threadIdx.x;
    int idx = blockIdx.x * 256 + t;
    int v = (idx < NN) ? g_cnt[idx] : 0;
    sh[t] = v;
    __syncthreads();
#pragma unroll
    for (int d = 1; d < 256; d <<= 1) {
        int o = (t >= d) ? sh[t - d] : 0;
        __syncthreads();
        sh[t] += o;
        __syncthreads();
    }
    if (idx < NN) g_rowptr[idx] = sh[t] - v;
    if (t == 255) g_blksum[blockIdx.x] = sh[255];
}

__global__ void scan2_kernel(int nblk) {
    __shared__ int sh[256];
    int t = threadIdx.x;
    int v = (t < nblk) ? g_blksum[t] : 0;
    sh[t] = v;
    __syncthreads();
#pragma unroll
    for (int d = 1; d < 256; d <<= 1) {
        int o = (t >= d) ? sh[t - d] : 0;
        __syncthreads();
        sh[t] += o;
        __syncthreads();
    }
    if (t < nblk) g_blkoff[t] = sh[t] - v;
    if (t == 255) g_rowptr[NN] = sh[255];
}

__global__ void scan3_kernel() {
    int idx = blockIdx.x * 256 + threadIdx.x;
    if (idx >= NN) return;
    int r = g_rowptr[idx] + g_blkoff[blockIdx.x];
    g_rowptr[idx] = r;
    g_cur[idx] = r;
}

__global__ void scatter_kernel(const int* __restrict__ ei) {
    int e = blockIdx.x * blockDim.x + threadIdx.x;
    if (e >= EE) return;
    int s = ei[e];
    int pos = atomicAdd(&g_cur[s], 1);
    g_dstidx[pos] = ei[EE + e];
}

// ---------------- GEMM (R5 version — at scalar-FFMA issue ceiling; untouched) ----------------
template <int K, bool HASBIAS>
__global__ void __launch_bounds__(256) gemm_kernel(const float* __restrict__ U,
                                                   const float* __restrict__ WT,
                                                   const float* __restrict__ bias,
                                                   float* __restrict__ P) {
    constexpr int TM = (K > 128) ? 56 : 64;
    constexpr int RPT = TM / 8;
    constexpr int K4 = K / 4;
    __shared__ __align__(16) float4 xs[TM * K4];
    int tid = threadIdx.x;
    int cg = tid & 31;
    int rg = tid >> 5;
    int row0 = blockIdx.x * TM;

    for (int i = tid; i < TM * K4; i += 256) {
        int m = i / K4, k4 = i - m * K4;
        int r = row0 + m;
        xs[i] = (r < NN) ? ((const float4*)(U + (size_t)r * K))[k4]
                         : make_float4(0.f, 0.f, 0.f, 0.f);
    }
    __syncthreads();

    float acc[RPT][4];
#pragma unroll
    for (int r = 0; r < RPT; r++) {
        acc[r][0] = 0.f; acc[r][1] = 0.f; acc[r][2] = 0.f; acc[r][3] = 0.f;
    }

    const float4* W4 = (const float4*)WT;
#pragma unroll 4
    for (int kq = 0; kq < K4; kq++) {
        float4 w0 = W4[(kq * 4 + 0) * 32 + cg];
        float4 w1 = W4[(kq * 4 + 1) * 32 + cg];
        float4 w2 = W4[(kq * 4 + 2) * 32 + cg];
        float4 w3 = W4[(kq * 4 + 3) * 32 + cg];
#pragma unroll
        for (int r = 0; r < RPT; r++) {
            float4 xv = xs[(rg * RPT + r) * K4 + kq];
            acc[r][0] = fmaf(xv.x, w0.x, acc[r][0]);
            acc[r][1] = fmaf(xv.x, w0.y, acc[r][1]);
            acc[r][2] = fmaf(xv.x, w0.z, acc[r][2]);
            acc[r][3] = fmaf(xv.x, w0.w, acc[r][3]);
            acc[r][0] = fmaf(xv.y, w1.x, acc[r][0]);
            acc[r][1] = fmaf(xv.y, w1.y, acc[r][1]);
            acc[r][2] = fmaf(xv.y, w1.z, acc[r][2]);
            acc[r][3] = fmaf(xv.y, w1.w, acc[r][3]);
            acc[r][0] = fmaf(xv.z, w2.x, acc[r][0]);
            acc[r][1] = fmaf(xv.z, w2.y, acc[r][1]);
            acc[r][2] = fmaf(xv.z, w2.z, acc[r][2]);
            acc[r][3] = fmaf(xv.z, w2.w, acc[r][3]);
            acc[r][0] = fmaf(xv.w, w3.x, acc[r][0]);
            acc[r][1] = fmaf(xv.w, w3.y, acc[r][1]);
            acc[r][2] = fmaf(xv.w, w3.z, acc[r][2]);
            acc[r][3] = fmaf(xv.w, w3.w, acc[r][3]);
        }
    }

    float4 bv = make_float4(0.f, 0.f, 0.f, 0.f);
    if (HASBIAS) {
        int j0 = 4 * cg;
        bv.x = (j0 + 0 < DD) ? bias[j0 + 0] : 0.f;
        bv.y = (j0 + 1 < DD) ? bias[j0 + 1] : 0.f;
        bv.z = (j0 + 2 < DD) ? bias[j0 + 2] : 0.f;
        bv.w = (j0 + 3 < DD) ? bias[j0 + 3] : 0.f;
    }
#pragma unroll
    for (int r = 0; r < RPT; r++) {
        int gr = row0 + rg * RPT + r;
        if (gr < NN) {
            float4 res;
            res.x = acc[r][0] + bv.x;
            res.y = acc[r][1] + bv.y;
            res.z = acc[r][2] + bv.z;
            res.w = (cg == 31) ? 0.f : acc[r][3] + bv.w;
            ((float4*)(P + (size_t)gr * HD))[cg] = res;
        }
    }
}

// ---------------- warp-per-node elementwise kernels ----------------

// logmap0 of hyperboloid o (register values == stored values): emits u quad.
// ss = sum of spatial squares (already warp-reduced), x0 = time component (uniform).
__device__ __forceinline__ float4 logmap_quad(float4 o, float ss, float x0,
                                              float c, float sc, int lane) {
    float yn = fmaxf(sqrtf(ss), 1e-9f);
    float d = sc * acoshf(fmaxf(x0 / sc, 1.f + EPSF));
    float a = d / yn;
    float nx = __shfl_down_sync(0xffffffffu, o.x, 1);
    float4 u;
    u.x = a * o.y; u.y = a * o.z; u.z = a * o.w;
    u.w = (lane == 31) ? 0.f : a * nx;
    return u;
}

// hl = proj(expmap0([0, P]))  (attention branch — no u needed)
__global__ void expmap_kernel(const float* __restrict__ P, float* __restrict__ out,
                              const float* __restrict__ cptr) {
    int warp = (blockIdx.x * blockDim.x + threadIdx.x) >> 5;
    int lane = threadIdx.x & 31;
    if (warp >= NN) return;
    float c = cptr[0], sc = sqrtf(c);
    float4 v = ((const float4*)(P + (size_t)warp * HD))[lane];
    float s = warp_sum(v.x * v.x + v.y * v.y + v.z * v.z + v.w * v.w);
    float n = fmaxf(sqrtf(s), 1e-9f);
    float sh = sc * sinhf(n / sc) / n;
    float wprev = __shfl_up_sync(0xffffffffu, v.w, 1);
    float4 o;
    o.x = (lane == 0) ? 0.f : sh * wprev;
    o.y = sh * v.x; o.z = sh * v.y; o.w = sh * v.z;
    float ss = warp_sum(((lane == 0) ? 0.f : o.x * o.x) + o.y * o.y + o.z * o.z + o.w * o.w);
    if (lane == 0) o.x = sqrtf(c + ss);
    ((float4*)(out + (size_t)warp * HD))[lane] = o;
}

// input stage: h = proj(expmap0([0, P])), u = logmap0(h)
__global__ void expmap_u_kernel(const float* __restrict__ P, float* __restrict__ H,
                                float* __restrict__ U, const float* __restrict__ cptr) {
    int warp = (blockIdx.x * blockDim.x + threadIdx.x) >> 5;
    int lane = threadIdx.x & 31;
    if (warp >= NN) return;
    float c = cptr[0], sc = sqrtf(c);
    float4 v = ((const float4*)(P + (size_t)warp * HD))[lane];
    float s = warp_sum(v.x * v.x + v.y * v.y + v.z * v.z + v.w * v.w);
    float n = fmaxf(sqrtf(s), 1e-9f);
    float sh = sc * sinhf(n / sc) / n;
    float wprev = __shfl_up_sync(0xffffffffu, v.w, 1);
    float4 o;
    o.x = (lane == 0) ? 0.f : sh * wprev;
    o.y = sh * v.x; o.z = sh * v.y; o.w = sh * v.z;
    float ss = warp_sum(((lane == 0) ? 0.f : o.x * o.x) + o.y * o.y + o.z * o.z + o.w * o.w);
    float x0 = sqrtf(c + ss);
    if (lane == 0) o.x = x0;
    ((float4*)(H + (size_t)warp * HD))[lane] = o;
    ((float4*)(U + (size_t)warp * HD))[lane] = logmap_quad(o, ss, x0, c, sc, lane);
}

// warp per node: CSR centroid + GIN combine; emits u = logmap0(result) ONLY
// (the combine output hyperboloid is consumed solely by the MLP's logmap).
__global__ void agg_combine_kernel(const float* __restrict__ hl, const float* __restrict__ h,
                                   float* __restrict__ U, const float* __restrict__ cptr,
                                   const float* __restrict__ epsp, int l) {
    int warp = (blockIdx.x * blockDim.x + threadIdx.x) >> 5;
    int lane = threadIdx.x & 31;
    if (warp >= NN) return;
    float c = cptr[0], sc = sqrtf(c), ep = epsp[l];
    bool c1 = (sc == 1.f);
    int beg = g_rowptr[warp], end = g_rowptr[warp + 1];
    float4 a = ((const float4*)(hl + (size_t)warp * HD))[lane];
    float ax0 = (lane == 0) ? -a.x : a.x;   // hoisted Lorentz sign
    float4 mv = make_float4(0.f, 0.f, 0.f, 0.f);
    int d = (beg < end) ? g_dstidx[beg] : 0;
    for (int e = beg; e < end; e++) {
        int dn = (e + 1 < end) ? g_dstidx[e + 1] : 0;
        float4 b = ((const float4*)(hl + (size_t)d * HD))[lane];
        float4 hv = ((const float4*)(h + (size_t)d * HD))[lane];
        float p = ax0 * b.x + a.y * b.y + a.z * b.z + a.w * b.w;
        p = warp_sum(p);
        float val = fmaxf(-p / c, 1.f + EPSF);
        // c==1: exp(-acosh(v)) == 1/(v + sqrt(v^2-1)) exactly (cheaper MUFU path)
        float att = c1 ? (1.f / (val + sqrtf(val * val - 1.f)))
                       : expf(-sc * acoshf(val));
        mv.x = fmaf(att, hv.x, mv.x);
        mv.y = fmaf(att, hv.y, mv.y);
        mv.z = fmaf(att, hv.z, mv.z);
        mv.w = fmaf(att, hv.w, mv.w);
        d = dn;
    }
    // combine (verbatim math)
    float4 hv = ((const float4*)(h + (size_t)warp * HD))[lane];
    float m0 = __shfl_sync(0xffffffffu, mv.x, 0);
    float pm = warp_sum(((lane == 0) ? 0.f : mv.x * mv.x) + mv.y * mv.y + mv.z * mv.z + mv.w * mv.w);
    float denom = sqrtf(fmaxf(m0 * m0 - pm, 1e-9f));
    float r = sc / denom;
    float axx = r * mv.x, ay = r * mv.y, az = r * mv.z, aw = r * mv.w;
    float ssum = warp_sum(((lane == 0) ? 0.f : axx * axx) + ay * ay + az * az + aw * aw);
    float t = sqrtf(c + ssum);
    float yn_a = fmaxf(sqrtf(ssum), 1e-9f);
    float d1 = sc * acoshf(fmaxf(t / sc, 1.f + EPSF));
    float cA = d1 / yn_a;
    float ph = warp_sum(((lane == 0) ? 0.f : hv.x * hv.x) + hv.y * hv.y + hv.z * hv.z + hv.w * hv.w);
    float hp0 = sqrtf(c + ph);
    float yn_h = fmaxf(sqrtf(ph), 1e-9f);
    float d2 = sc * acoshf(fmaxf(hp0 / sc, 1.f + EPSF));
    float cH = (1.f + ep) * d2 / yn_h;
    float4 vv;
    vv.x = (lane == 0) ? 0.f : cA * axx + cH * hv.x;
    vv.y = cA * ay + cH * hv.y;
    vv.z = cA * az + cH * hv.z;
    vv.w = cA * aw + cH * hv.w;
    float pv = warp_sum(vv.x * vv.x + vv.y * vv.y + vv.z * vv.z + vv.w * vv.w);
    float n = fmaxf(sqrtf(pv), 1e-9f);
    float sh = sc * sinhf(n / sc) / n;
    float4 o;
    o.x = (lane == 0) ? 0.f : sh * vv.x;
    o.y = sh * vv.y; o.z = sh * vv.z; o.w = sh * vv.w;
    float so = warp_sum(((lane == 0) ? 0.f : o.x * o.x) + o.y * o.y + o.z * o.z + o.w * o.w);
    float x0 = sqrtf(c + so);
    if (lane == 0) o.x = x0;
    ((float4*)(U + (size_t)warp * HD))[lane] = logmap_quad(o, so, x0, c, sc, lane);
}

// MLP epilogue: o = hyp_act(proj(expmap0([0,P]))); emits u = logmap0(o);
// optionally stores o (layer output) and pools logmap values into d_out.
template <bool WRITE_H, bool POOL>
__global__ void mlp_epi_kernel(const float* __restrict__ P, float* __restrict__ H,
                               float* __restrict__ U, const float* __restrict__ cptr,
                               const int* __restrict__ batch, float* __restrict__ out,
                               int loff) {
    int warp = (blockIdx.x * blockDim.x + threadIdx.x) >> 5;
    int lane = threadIdx.x & 31;
    if (warp >= NN) return;
    float c = cptr[0], sc = sqrtf(c);
    float4 v = ((const float4*)(P + (size_t)warp * HD))[lane];
    float s = warp_sum(v.x * v.x + v.y * v.y + v.z * v.z + v.w * v.w);
    float n1 = fmaxf(sqrtf(s), 1e-9f);
    float sh1 = sc * sinhf(n1 / sc) / n1;
    float sx = sh1 * v.x, sy = sh1 * v.y, sz = sh1 * v.z, sw = sh1 * v.w;
    float ssum = warp_sum(sx * sx + sy * sy + sz * sz + sw * sw);
    float x0p = sqrtf(c + ssum);
    float ynp = fmaxf(sqrtf(ssum), 1e-9f);
    float dp = sc * acoshf(fmaxf(x0p / sc, 1.f + EPSF));
    float cf = dp / ynp;
    float tx = tanhf(cf * sx), ty = tanhf(cf * sy), tz = tanhf(cf * sz), tw = tanhf(cf * sw);
    float s2 = warp_sum(tx * tx + ty * ty + tz * tz + tw * tw);
    float n2 = fmaxf(sqrtf(s2), 1e-9f);
    float sh2 = sc * sinhf(n2 / sc) / n2;
    float wprev = __shfl_up_sync(0xffffffffu, tw, 1);
    float x0 = sc * coshf(n2 / sc);   // warp-uniform time component
    float4 o;
    o.x = (lane == 0) ? x0 : sh2 * wprev;
    o.y = sh2 * tx; o.z = sh2 * ty; o.w = sh2 * tz;
    if (WRITE_H) ((float4*)(H + (size_t)warp * HD))[lane] = o;
    // logmap0 from stored values (exact lognode expression order)
    float sl = warp_sum(((lane == 0) ? 0.f : o.x * o.x) + o.y * o.y + o.z * o.z + o.w * o.w);
    float yn = fmaxf(sqrtf(sl), 1e-9f);
    float d = sc * acoshf(fmaxf(x0 / sc, 1.f + EPSF));
    float a = d / yn;
    float nx = __shfl_down_sync(0xffffffffu, o.x, 1);
    float4 u;
    u.x = a * o.y; u.y = a * o.z; u.z = a * o.w;
    u.w = (lane == 31) ? 0.f : a * nx;
    ((float4*)(U + (size_t)warp * HD))[lane] = u;
    if (POOL) {
        int g = batch[warp];
        red_v4(out + (size_t)g * (2 * HD) + loff + lane * 4,
               (lane == 0) ? 0.f : a * o.x, a * o.y, a * o.z, a * o.w);
    }
}

// ---------------- host launcher ----------------
extern "C" void kernel_launch(void* const* d_in, const int* in_sizes, int n_in,
                              void* d_out, int out_size) {
    (void)in_sizes; (void)n_in; (void)out_size;
    const float* x     = (const float*)d_in[0];
    const float* c     = (const float*)d_in[1];
    const float* w_in  = (const float*)d_in[2];
    const float* att_w = (const float*)d_in[3];
    const float* att_b = (const float*)d_in[4];
    const float* eps   = (const float*)d_in[5];
    const float* mlp_w = (const float*)d_in[6];
    const float* mlp_b = (const float*)d_in[7];
    const int*   ei    = (const int*)d_in[8];
    const int*   batch = (const int*)d_in[9];
    float* out = (float*)d_out;

    float *ph, *pu, *pp, *phl, *pwt, *pwtin;
    int* pcnt;
    cudaGetSymbolAddress((void**)&ph, g_h);
    cudaGetSymbolAddress((void**)&pu, g_u);
    cudaGetSymbolAddress((void**)&pp, g_p);
    cudaGetSymbolAddress((void**)&phl, g_hl);
    cudaGetSymbolAddress((void**)&pwt, g_wt);
    cudaGetSymbolAddress((void**)&pwtin, g_wtin);
    cudaGetSymbolAddress((void**)&pcnt, g_cnt);

    const int NB = (NN + 7) / 8;
    const int GB200 = (NN + 55) / 56;
    const int GB128 = (NN + 63) / 64;
    const int SCB = (NN + 255) / 256;

    zero4_kernel<<<(GG * 2 * HD / 4 + 255) / 256, 256>>>((float4*)out, GG * 2 * HD / 4);
    prep_weights<<<(6 * HD * HD + 255) / 256, 256>>>(att_w, mlp_w);
    prep_win<<<(IN_DIM * HD + 255) / 256, 256>>>(w_in);

    // CSR build (once; reused by both layers)
    zeroi_kernel<<<SCB, 256>>>(pcnt, NN);
    hist_kernel<<<(EE + 255) / 256, 256>>>(ei);
    scan1_kernel<<<SCB, 256>>>();
    scan2_kernel<<<1, 256>>>(SCB);
    scan3_kernel<<<SCB, 256>>>();
    scatter_kernel<<<(EE + 255) / 256, 256>>>(ei);

    // input: h0 = proj(expmap0([0, x @ w_in])), u0 = logmap0(h0)
    gemm_kernel<IN_DIM, false><<<GB200, 256>>>(x, pwtin, nullptr, pp);
    expmap_u_kernel<<<NB, 256>>>(pp, ph, pu, c);

    for (int l = 0; l < 2; l++) {
        // attention linear: hl = proj(expmap0(u @ W + b))
        gemm_kernel<HD, true><<<GB128, 256>>>(pu, pwt + l * HD * HD, att_b + l * DD, pp);
        expmap_kernel<<<NB, 256>>>(pp, phl, c);
        // centroid + GIN combine -> u (logmap of combined point)
        agg_combine_kernel<<<NB, 256>>>(phl, ph, pu, c, eps, l);
        // MLP 0: u only
        gemm_kernel<HD, true><<<GB128, 256>>>(pu, pwt + (2 + l * 2 + 0) * HD * HD,
                                              mlp_b + (l * 2 + 0) * DD, pp);
        mlp_epi_kernel<false, false><<<NB, 256>>>(pp, nullptr, pu, c, nullptr, nullptr, 0);
        // MLP 1: h (next layer's agg input) + u (next att GEMM / pool) + pooled readout
        gemm_kernel<HD, true><<<GB128, 256>>>(pu, pwt + (2 + l * 2 + 1) * HD * HD,
                                              mlp_b + (l * 2 + 1) * DD, pp);
        mlp_epi_kernel<true, true><<<NB, 256>>>(pp, ph, pu, c, batch, out, l * HD);
    }
}

// round 9
// speedup vs baseline: 1.1898x; 1.0460x over previous
#include <cuda_runtime.h>
#include <math.h>
#include <stdint.h>

#define NN 50000
#define EE 800000
#define IN_DIM 200
#define HD 128
#define DD 127
#define GG 512
#define EPSF 1e-5f

// ---------------- scratch (device globals; no allocation allowed) ----------------
__device__ float g_h[NN * HD];      // hyperboloid node features
__device__ float g_u[NN * HD];      // logmap0 spatial (slots 0..126, slot127 = 0)
__device__ float g_p[NN * HD];      // GEMM output
__device__ float g_hl[NN * HD];     // attention-linear hyperboloid points
__device__ float g_wt[6 * HD * HD];   // transposed+padded weights (k-major)
__device__ float g_wtin[IN_DIM * HD];
__device__ float g_wf[6 * 16 * 16 * 32 * 4];    // fragment-ordered split weights (K=128 mats)
__device__ float g_wfin[25 * 16 * 32 * 4];      // fragment-ordered split input weights (K=200)
__device__ int   g_cnt[NN];
__device__ int   g_rowptr[NN + 1];
__device__ int   g_cur[NN];
__device__ int   g_dstidx[EE];
__device__ int   g_blksum[256];
__device__ int   g_blkoff[256];

__device__ __forceinline__ float warp_sum(float v) {
#pragma unroll
    for (int o = 16; o; o >>= 1) v += __shfl_xor_sync(0xffffffffu, v, o);
    return v;
}

__device__ __forceinline__ void red_v4(float* p, float a, float b, float c, float d) {
    asm volatile("red.global.add.v4.f32 [%0], {%1,%2,%3,%4};"
                 :: "l"(p), "f"(a), "f"(b), "f"(c), "f"(d) : "memory");
}

// m16n8k8 tf32 MMA, fp32 accumulate (A row-major frag, B col-major frag)
__device__ __forceinline__ void mma_tf32(float* d, uint32_t a0, uint32_t a1,
                                         uint32_t a2, uint32_t a3,
                                         uint32_t b0, uint32_t b1) {
    asm("mma.sync.aligned.m16n8k8.row.col.f32.tf32.tf32.f32 "
        "{%0,%1,%2,%3}, {%4,%5,%6,%7}, {%8,%9}, {%0,%1,%2,%3};"
        : "+f"(d[0]), "+f"(d[1]), "+f"(d[2]), "+f"(d[3])
        : "r"(a0), "r"(a1), "r"(a2), "r"(a3), "r"(b0), "r"(b1));
}

__device__ __forceinline__ uint32_t tf32_hi_bits(float x) {
    return __float_as_uint(x) & 0xFFFFE000u;   // truncate to 10-bit mantissa (exact tf32)
}

// ---------------- utility kernels ----------------
__global__ void zero4_kernel(float4* __restrict__ p, int n4) {
    int i = blockIdx.x * blockDim.x + threadIdx.x;
    if (i < n4) p[i] = make_float4(0.f, 0.f, 0.f, 0.f);
}

__global__ void zeroi_kernel(int* __restrict__ p, int n) {
    int i = blockIdx.x * blockDim.x + threadIdx.x;
    if (i < n) p[i] = 0;
}

__global__ void prep_weights(const float* __restrict__ att_w, const float* __restrict__ mlp_w) {
    int idx = blockIdx.x * blockDim.x + threadIdx.x;
    if (idx >= 6 * HD * HD) return;
    int w = idx >> 14;
    int k = (idx >> 7) & 127;
    int j = idx & 127;
    float val = 0.f;
    if (k < DD && j < DD) {
        const float* src = (w < 2) ? (att_w + w * DD * DD) : (mlp_w + (w - 2) * DD * DD);
        val = src[j * DD + k];
    }
    g_wt[idx] = val;
}

__global__ void prep_win(const float* __restrict__ w_in) {
    int idx = blockIdx.x * blockDim.x + threadIdx.x;
    if (idx >= IN_DIM * HD) return;
    int k = idx >> 7;
    int j = idx & 127;
    g_wtin[idx] = (j < DD) ? w_in[k * DD + j] : 0.f;
}

// fragment-ordered split weights: float4 (b0h, b1h, b0l, b1l) per (mat, k8, tile, lane)
__global__ void prep_wf() {
    int idx = blockIdx.x * blockDim.x + threadIdx.x;
    if (idx >= 6 * 16 * 16 * 32) return;
    int lane = idx & 31;
    int tile = (idx >> 5) & 15;
    int k8 = (idx >> 9) & 15;
    int mat = idx >> 13;
    int gg = lane >> 2, t4 = lane & 3;
    int k0 = k8 * 8 + t4;
    int n = tile * 8 + gg;
    float b0 = g_wt[mat * HD * HD + k0 * HD + n];
    float b1 = g_wt[mat * HD * HD + (k0 + 4) * HD + n];
    float4 o;
    o.x = __uint_as_float(tf32_hi_bits(b0));
    o.y = __uint_as_float(tf32_hi_bits(b1));
    o.z = b0 - o.x;
    o.w = b1 - o.y;
    ((float4*)g_wf)[idx] = o;
}

__global__ void prep_wfin() {
    int idx = blockIdx.x * blockDim.x + threadIdx.x;
    if (idx >= 25 * 16 * 32) return;
    int lane = idx & 31;
    int tile = (idx >> 5) & 15;
    int k8 = idx >> 9;                 // 0..24
    int gg = lane >> 2, t4 = lane & 3;
    int k0 = k8 * 8 + t4;
    int n = tile * 8 + gg;
    float b0 = g_wtin[k0 * HD + n];
    float b1 = g_wtin[(k0 + 4) * HD + n];
    float4 o;
    o.x = __uint_as_float(tf32_hi_bits(b0));
    o.y = __uint_as_float(tf32_hi_bits(b1));
    o.z = b0 - o.x;
    o.w = b1 - o.y;
    ((float4*)g_wfin)[idx] = o;
}

// ---------------- CSR build ----------------
__global__ void hist_kernel(const int* __restrict__ ei) {
    int e = blockIdx.x * blockDim.x + threadIdx.x;
    if (e < EE) atomicAdd(&g_cnt[ei[e]], 1);
}

__global__ void scan1_kernel() {
    __shared__ int sh[256];
    int t = threadIdx.x;
    int idx = blockIdx.x * 256 + t;
    int v = (idx < NN) ? g_cnt[idx] : 0;
    sh[t] = v;
    __syncthreads();
#pragma unroll
    for (int d = 1; d < 256; d <<= 1) {
        int o = (t >= d) ? sh[t - d] : 0;
        __syncthreads();
        sh[t] += o;
        __syncthreads();
    }
    if (idx < NN) g_rowptr[idx] = sh[t] - v;
    if (t == 255) g_blksum[blockIdx.x] = sh[255];
}

__global__ void scan2_kernel(int nblk) {
    __shared__ int sh[256];
    int t = threadIdx.x;
    int v = (t < nblk) ? g_blksum[t] : 0;
    sh[t] = v;
    __syncthreads();
#pragma unroll
    for (int d = 1; d < 256; d <<= 1) {
        int o = (t >= d) ? sh[t - d] : 0;
        __syncthreads();
        sh[t] += o;
        __syncthreads();
    }
    if (t < nblk) g_blkoff[t] = sh[t] - v;
    if (t == 255) g_rowptr[NN] = sh[255];
}

__global__ void scan3_kernel() {
    int idx = blockIdx.x * 256 + threadIdx.x;
    if (idx >= NN) return;
    int r = g_rowptr[idx] + g_blkoff[blockIdx.x];
    g_rowptr[idx] = r;
    g_cur[idx] = r;
}

__global__ void scatter_kernel(const int* __restrict__ ei) {
    int e = blockIdx.x * blockDim.x + threadIdx.x;
    if (e >= EE) return;
    int s = ei[e];
    int pos = atomicAdd(&g_cur[s], 1);
    g_dstidx[pos] = ei[EE + e];
}

// ---------------- split-TF32 tensor-core GEMM ----------------
// P[n][j] = sum_k U[n][k] * W[k][j] (+ bias), error ~2^-19 (hi/lo split, 3 MMAs).
// Block: 256 threads = 8 warps = 4 m-warps x 2 n-warps; tile 64 rows x 128 cols.
// Warp (wm, wn): rows 16*wm.., cols 64*wn.. as 8 n8-tiles of m16n8k8.
// B pre-packed in fragment order (one LDG.128 -> hi+lo fragments); A loaded
// directly from L2 (no smem, no barriers). Output layout identical to old GEMM.
template <int K, bool HASBIAS>
__global__ void __launch_bounds__(256) gemm_tc(const float* __restrict__ U,
                                               const float4* __restrict__ WF,
                                               const float* __restrict__ bias,
                                               float* __restrict__ P) {
    constexpr int K8 = K / 8;
    int tid = threadIdx.x;
    int lane = tid & 31;
    int w = tid >> 5;
    int wm = w & 3;
    int wn = w >> 2;
    int row0 = blockIdx.x * 64;
    int gg = lane >> 2, t4 = lane & 3;
    int ra = row0 + 16 * wm + gg;
    int rb = ra + 8;
    const float* A0 = U + (size_t)min(ra, NN - 1) * K;  // clamped: garbage rows never stored
    const float* A1 = U + (size_t)min(rb, NN - 1) * K;

    float acc[8][4];
#pragma unroll
    for (int t = 0; t < 8; t++) {
        acc[t][0] = 0.f; acc[t][1] = 0.f; acc[t][2] = 0.f; acc[t][3] = 0.f;
    }

    for (int k8 = 0; k8 < K8; k8++) {
        int kc = k8 * 8;
        float a0 = A0[kc + t4];
        float a1 = A1[kc + t4];
        float a2 = A0[kc + 4 + t4];
        float a3 = A1[kc + 4 + t4];
        uint32_t h0 = tf32_hi_bits(a0), h1 = tf32_hi_bits(a1);
        uint32_t h2 = tf32_hi_bits(a2), h3 = tf32_hi_bits(a3);
        uint32_t l0 = __float_as_uint(a0 - __uint_as_float(h0));
        uint32_t l1 = __float_as_uint(a1 - __uint_as_float(h1));
        uint32_t l2 = __float_as_uint(a2 - __uint_as_float(h2));
        uint32_t l3 = __float_as_uint(a3 - __uint_as_float(h3));
        const float4* wf = WF + ((size_t)k8 * 16 + wn * 8) * 32 + lane;
#pragma unroll
        for (int t = 0; t < 8; t++) {
            float4 bv = wf[t * 32];   // (b0h, b1h, b0l, b1l)
            uint32_t b0h = __float_as_uint(bv.x), b1h = __float_as_uint(bv.y);
            uint32_t b0l = __float_as_uint(bv.z), b1l = __float_as_uint(bv.w);
            mma_tf32(acc[t], h0, h1, h2, h3, b0h, b1h);  // hi*hi
            mma_tf32(acc[t], h0, h1, h2, h3, b0l, b1l);  // hi*lo
            mma_tf32(acc[t], l0, l1, l2, l3, b0h, b1h);  // lo*hi
        }
    }

#pragma unroll
    for (int t = 0; t < 8; t++) {
        int j0 = 64 * wn + 8 * t + 2 * t4;   // even, 0..126
        float b0 = 0.f, b1 = 0.f;
        if (HASBIAS) {
            b0 = bias[j0];                       // j0 <= 126 < DD always
            b1 = (j0 + 1 < DD) ? bias[j0 + 1] : 0.f;
        }
        float d0 = acc[t][0] + b0, d1 = acc[t][1] + b1;
        float d2 = acc[t][2] + b0, d3 = acc[t][3] + b1;
        if (j0 + 1 == 127) { d1 = 0.f; d3 = 0.f; }  // padding col
        if (ra < NN) *(float2*)&P[(size_t)ra * HD + j0] = make_float2(d0, d1);
        if (rb < NN) *(float2*)&P[(size_t)rb * HD + j0] = make_float2(d2, d3);
    }
}

// ---------------- warp-per-node elementwise kernels (unchanged from R7) ----------------

__device__ __forceinline__ float4 logmap_quad(float4 o, float ss, float x0,
                                              float c, float sc, int lane) {
    float yn = fmaxf(sqrtf(ss), 1e-9f);
    float d = sc * acoshf(fmaxf(x0 / sc, 1.f + EPSF));
    float a = d / yn;
    float nx = __shfl_down_sync(0xffffffffu, o.x, 1);
    float4 u;
    u.x = a * o.y; u.y = a * o.z; u.z = a * o.w;
    u.w = (lane == 31) ? 0.f : a * nx;
    return u;
}

__global__ void expmap_kernel(const float* __restrict__ P, float* __restrict__ out,
                              const float* __restrict__ cptr) {
    int warp = (blockIdx.x * blockDim.x + threadIdx.x) >> 5;
    int lane = threadIdx.x & 31;
    if (warp >= NN) return;
    float c = cptr[0], sc = sqrtf(c);
    float4 v = ((const float4*)(P + (size_t)warp * HD))[lane];
    float s = warp_sum(v.x * v.x + v.y * v.y + v.z * v.z + v.w * v.w);
    float n = fmaxf(sqrtf(s), 1e-9f);
    float sh = sc * sinhf(n / sc) / n;
    float wprev = __shfl_up_sync(0xffffffffu, v.w, 1);
    float4 o;
    o.x = (lane == 0) ? 0.f : sh * wprev;
    o.y = sh * v.x; o.z = sh * v.y; o.w = sh * v.z;
    float ss = warp_sum(((lane == 0) ? 0.f : o.x * o.x) + o.y * o.y + o.z * o.z + o.w * o.w);
    if (lane == 0) o.x = sqrtf(c + ss);
    ((float4*)(out + (size_t)warp * HD))[lane] = o;
}

__global__ void expmap_u_kernel(const float* __restrict__ P, float* __restrict__ H,
                                float* __restrict__ U, const float* __restrict__ cptr) {
    int warp = (blockIdx.x * blockDim.x + threadIdx.x) >> 5;
    int lane = threadIdx.x & 31;
    if (warp >= NN) return;
    float c = cptr[0], sc = sqrtf(c);
    float4 v = ((const float4*)(P + (size_t)warp * HD))[lane];
    float s = warp_sum(v.x * v.x + v.y * v.y + v.z * v.z + v.w * v.w);
    float n = fmaxf(sqrtf(s), 1e-9f);
    float sh = sc * sinhf(n / sc) / n;
    float wprev = __shfl_up_sync(0xffffffffu, v.w, 1);
    float4 o;
    o.x = (lane == 0) ? 0.f : sh * wprev;
    o.y = sh * v.x; o.z = sh * v.y; o.w = sh * v.z;
    float ss = warp_sum(((lane == 0) ? 0.f : o.x * o.x) + o.y * o.y + o.z * o.z + o.w * o.w);
    float x0 = sqrtf(c + ss);
    if (lane == 0) o.x = x0;
    ((float4*)(H + (size_t)warp * HD))[lane] = o;
    ((float4*)(U + (size_t)warp * HD))[lane] = logmap_quad(o, ss, x0, c, sc, lane);
}

__global__ void agg_combine_kernel(const float* __restrict__ hl, const float* __restrict__ h,
                                   float* __restrict__ U, const float* __restrict__ cptr,
                                   const float* __restrict__ epsp, int l) {
    int warp = (blockIdx.x * blockDim.x + threadIdx.x) >> 5;
    int lane = threadIdx.x & 31;
    if (warp >= NN) return;
    float c = cptr[0], sc = sqrtf(c), ep = epsp[l];
    bool c1 = (sc == 1.f);
    int beg = g_rowptr[warp], end = g_rowptr[warp + 1];
    float4 a = ((const float4*)(hl + (size_t)warp * HD))[lane];
    float ax0 = (lane == 0) ? -a.x : a.x;
    float4 mv = make_float4(0.f, 0.f, 0.f, 0.f);
    int d = (beg < end) ? g_dstidx[beg] : 0;
    for (int e = beg; e < end; e++) {
        int dn = (e + 1 < end) ? g_dstidx[e + 1] : 0;
        float4 b = ((const float4*)(hl + (size_t)d * HD))[lane];
        float4 hv = ((const float4*)(h + (size_t)d * HD))[lane];
        float p = ax0 * b.x + a.y * b.y + a.z * b.z + a.w * b.w;
        p = warp_sum(p);
        float val = fmaxf(-p / c, 1.f + EPSF);
        float att = c1 ? (1.f / (val + sqrtf(val * val - 1.f)))
                       : expf(-sc * acoshf(val));
        mv.x = fmaf(att, hv.x, mv.x);
        mv.y = fmaf(att, hv.y, mv.y);
        mv.z = fmaf(att, hv.z, mv.z);
        mv.w = fmaf(att, hv.w, mv.w);
        d = dn;
    }
    float4 hv = ((const float4*)(h + (size_t)warp * HD))[lane];
    float m0 = __shfl_sync(0xffffffffu, mv.x, 0);
    float pm = warp_sum(((lane == 0) ? 0.f : mv.x * mv.x) + mv.y * mv.y + mv.z * mv.z + mv.w * mv.w);
    float denom = sqrtf(fmaxf(m0 * m0 - pm, 1e-9f));
    float r = sc / denom;
    float axx = r * mv.x, ay = r * mv.y, az = r * mv.z, aw = r * mv.w;
    float ssum = warp_sum(((lane == 0) ? 0.f : axx * axx) + ay * ay + az * az + aw * aw);
    float t = sqrtf(c + ssum);
    float yn_a = fmaxf(sqrtf(ssum), 1e-9f);
    float d1 = sc * acoshf(fmaxf(t / sc, 1.f + EPSF));
    float cA = d1 / yn_a;
    float ph = warp_sum(((lane == 0) ? 0.f : hv.x * hv.x) + hv.y * hv.y + hv.z * hv.z + hv.w * hv.w);
    float hp0 = sqrtf(c + ph);
    float yn_h = fmaxf(sqrtf(ph), 1e-9f);
    float d2 = sc * acoshf(fmaxf(hp0 / sc, 1.f + EPSF));
    float cH = (1.f + ep) * d2 / yn_h;
    float4 vv;
    vv.x = (lane == 0) ? 0.f : cA * axx + cH * hv.x;
    vv.y = cA * ay + cH * hv.y;
    vv.z = cA * az + cH * hv.z;
    vv.w = cA * aw + cH * hv.w;
    float pv = warp_sum(vv.x * vv.x + vv.y * vv.y + vv.z * vv.z + vv.w * vv.w);
    float n = fmaxf(sqrtf(pv), 1e-9f);
    float sh = sc * sinhf(n / sc) / n;
    float4 o;
    o.x = (lane == 0) ? 0.f : sh * vv.x;
    o.y = sh * vv.y; o.z = sh * vv.z; o.w = sh * vv.w;
    float so = warp_sum(((lane == 0) ? 0.f : o.x * o.x) + o.y * o.y + o.z * o.z + o.w * o.w);
    float x0 = sqrtf(c + so);
    if (lane == 0) o.x = x0;
    ((float4*)(U + (size_t)warp * HD))[lane] = logmap_quad(o, so, x0, c, sc, lane);
}

template <bool WRITE_H, bool POOL>
__global__ void mlp_epi_kernel(const float* __restrict__ P, float* __restrict__ H,
                               float* __restrict__ U, const float* __restrict__ cptr,
                               const int* __restrict__ batch, float* __restrict__ out,
                               int loff) {
    int warp = (blockIdx.x * blockDim.x + threadIdx.x) >> 5;
    int lane = threadIdx.x & 31;
    if (warp >= NN) return;
    float c = cptr[0], sc = sqrtf(c);
    float4 v = ((const float4*)(P + (size_t)warp * HD))[lane];
    float s = warp_sum(v.x * v.x + v.y * v.y + v.z * v.z + v.w * v.w);
    float n1 = fmaxf(sqrtf(s), 1e-9f);
    float sh1 = sc * sinhf(n1 / sc) / n1;
    float sx = sh1 * v.x, sy = sh1 * v.y, sz = sh1 * v.z, sw = sh1 * v.w;
    float ssum = warp_sum(sx * sx + sy * sy + sz * sz + sw * sw);
    float x0p = sqrtf(c + ssum);
    float ynp = fmaxf(sqrtf(ssum), 1e-9f);
    float dp = sc * acoshf(fmaxf(x0p / sc, 1.f + EPSF));
    float cf = dp / ynp;
    float tx = tanhf(cf * sx), ty = tanhf(cf * sy), tz = tanhf(cf * sz), tw = tanhf(cf * sw);
    float s2 = warp_sum(tx * tx + ty * ty + tz * tz + tw * tw);
    float n2 = fmaxf(sqrtf(s2), 1e-9f);
    float sh2 = sc * sinhf(n2 / sc) / n2;
    float wprev = __shfl_up_sync(0xffffffffu, tw, 1);
    float x0 = sc * coshf(n2 / sc);
    float4 o;
    o.x = (lane == 0) ? x0 : sh2 * wprev;
    o.y = sh2 * tx; o.z = sh2 * ty; o.w = sh2 * tz;
    if (WRITE_H) ((float4*)(H + (size_t)warp * HD))[lane] = o;
    float sl = warp_sum(((lane == 0) ? 0.f : o.x * o.x) + o.y * o.y + o.z * o.z + o.w * o.w);
    float yn = fmaxf(sqrtf(sl), 1e-9f);
    float d = sc * acoshf(fmaxf(x0 / sc, 1.f + EPSF));
    float a = d / yn;
    float nx = __shfl_down_sync(0xffffffffu, o.x, 1);
    float4 u;
    u.x = a * o.y; u.y = a * o.z; u.z = a * o.w;
    u.w = (lane == 31) ? 0.f : a * nx;
    ((float4*)(U + (size_t)warp * HD))[lane] = u;
    if (POOL) {
        int g = batch[warp];
        red_v4(out + (size_t)g * (2 * HD) + loff + lane * 4,
               (lane == 0) ? 0.f : a * o.x, a * o.y, a * o.z, a * o.w);
    }
}

// ---------------- host launcher ----------------
extern "C" void kernel_launch(void* const* d_in, const int* in_sizes, int n_in,
                              void* d_out, int out_size) {
    (void)in_sizes; (void)n_in; (void)out_size;
    const float* x     = (const float*)d_in[0];
    const float* c     = (const float*)d_in[1];
    const float* w_in  = (const float*)d_in[2];
    const float* att_w = (const float*)d_in[3];
    const float* att_b = (const float*)d_in[4];
    const float* eps   = (const float*)d_in[5];
    const float* mlp_w = (const float*)d_in[6];
    const float* mlp_b = (const float*)d_in[7];
    const int*   ei    = (const int*)d_in[8];
    const int*   batch = (const int*)d_in[9];
    float* out = (float*)d_out;

    float *ph, *pu, *pp, *phl, *pwf, *pwfin;
    int* pcnt;
    cudaGetSymbolAddress((void**)&ph, g_h);
    cudaGetSymbolAddress((void**)&pu, g_u);
    cudaGetSymbolAddress((void**)&pp, g_p);
    cudaGetSymbolAddress((void**)&phl, g_hl);
    cudaGetSymbolAddress((void**)&pwf, g_wf);
    cudaGetSymbolAddress((void**)&pwfin, g_wfin);
    cudaGetSymbolAddress((void**)&pcnt, g_cnt);

    const int NB = (NN + 7) / 8;        // warp-per-node blocks
    const int TB = (NN + 63) / 64;      // tensor GEMM blocks (64 rows each)
    const int SCB = (NN + 255) / 256;   // scan blocks

    zero4_kernel<<<(GG * 2 * HD / 4 + 255) / 256, 256>>>((float4*)out, GG * 2 * HD / 4);
    prep_weights<<<(6 * HD * HD + 255) / 256, 256>>>(att_w, mlp_w);
    prep_win<<<(IN_DIM * HD + 255) / 256, 256>>>(w_in);
    prep_wf<<<(6 * 16 * 16 * 32 + 255) / 256, 256>>>();
    prep_wfin<<<(25 * 16 * 32 + 255) / 256, 256>>>();

    // CSR build (once; reused by both layers)
    zeroi_kernel<<<SCB, 256>>>(pcnt, NN);
    hist_kernel<<<(EE + 255) / 256, 256>>>(ei);
    scan1_kernel<<<SCB, 256>>>();
    scan2_kernel<<<1, 256>>>(SCB);
    scan3_kernel<<<SCB, 256>>>();
    scatter_kernel<<<(EE + 255) / 256, 256>>>(ei);

    // input: h0 = proj(expmap0([0, x @ w_in])), u0 = logmap0(h0)
    gemm_tc<IN_DIM, false><<<TB, 256>>>(x, (const float4*)pwfin, nullptr, pp);
    expmap_u_kernel<<<NB, 256>>>(pp, ph, pu, c);

    for (int l = 0; l < 2; l++) {
        // attention linear: hl = proj(expmap0(u @ W + b))
        gemm_tc<HD, true><<<TB, 256>>>(pu, (const float4*)(pwf + (size_t)l * 16 * 16 * 32 * 4),
                                       att_b + l * DD, pp);
        expmap_kernel<<<NB, 256>>>(pp, phl, c);
        // centroid + GIN combine -> u
        agg_combine_kernel<<<NB, 256>>>(phl, ph, pu, c, eps, l);
        // MLP 0
        gemm_tc<HD, true><<<TB, 256>>>(pu, (const float4*)(pwf + (size_t)(2 + l * 2 + 0) * 16 * 16 * 32 * 4),
                                       mlp_b + (l * 2 + 0) * DD, pp);
        mlp_epi_kernel<false, false><<<NB, 256>>>(pp, nullptr, pu, c, nullptr, nullptr, 0);
        // MLP 1 (+ layer output + pooled readout)
        gemm_tc<HD, true><<<TB, 256>>>(pu, (const float4*)(pwf + (size_t)(2 + l * 2 + 1) * 16 * 16 * 32 * 4),
                                       mlp_b + (l * 2 + 1) * DD, pp);
        mlp_epi_kernel<true, true><<<NB, 256>>>(pp, ph, pu, c, batch, out, l * HD);
    }
}

// round 10
// speedup vs baseline: 1.4397x; 1.2100x over previous
#include <cuda_runtime.h>
#include <math.h>
#include <stdint.h>

#define NN 50000
#define EE 800000
#define IN_DIM 200
#define HD 128
#define DD 127
#define GG 512
#define EPSF 1e-5f

// ---------------- scratch (device globals; no allocation allowed) ----------------
__device__ float g_h[NN * HD];      // hyperboloid node features
__device__ float g_u[NN * HD];      // logmap0 spatial (slots 0..126, slot127 = 0)
__device__ float g_p[NN * HD];      // GEMM output
__device__ float g_hl[NN * HD];     // attention-linear hyperboloid points
__device__ float g_wt[6 * HD * HD];   // transposed+padded weights (k-major)
__device__ float g_wtin[IN_DIM * HD];
__device__ float g_wf[6 * 8 * 16 * 32 * 4];     // bf16-split fragment weights (K=128 mats)
__device__ float g_wfin[13 * 16 * 32 * 4];      // bf16-split fragment input weights (K=200->208)
__device__ int   g_cnt[NN];
__device__ int   g_rowptr[NN + 1];
__device__ int   g_cur[NN];
__device__ int   g_dstidx[EE];
__device__ int   g_blksum[256];
__device__ int   g_blkoff[256];

__device__ __forceinline__ float warp_sum(float v) {
#pragma unroll
    for (int o = 16; o; o >>= 1) v += __shfl_xor_sync(0xffffffffu, v, o);
    return v;
}

__device__ __forceinline__ void red_v4(float* p, float a, float b, float c, float d) {
    asm volatile("red.global.add.v4.f32 [%0], {%1,%2,%3,%4};"
                 :: "l"(p), "f"(a), "f"(b), "f"(c), "f"(d) : "memory");
}

// m16n8k16 bf16 MMA, fp32 accumulate (A row-major frag, B col-major frag)
__device__ __forceinline__ void mma_bf16(float* d, uint32_t a0, uint32_t a1,
                                         uint32_t a2, uint32_t a3,
                                         uint32_t b0, uint32_t b1) {
    asm("mma.sync.aligned.m16n8k16.row.col.f32.bf16.bf16.f32 "
        "{%0,%1,%2,%3}, {%4,%5,%6,%7}, {%8,%9}, {%0,%1,%2,%3};"
        : "+f"(d[0]), "+f"(d[1]), "+f"(d[2]), "+f"(d[3])
        : "r"(a0), "r"(a1), "r"(a2), "r"(a3), "r"(b0), "r"(b1));
}

// pack two floats into bf16x2 (lower half = x, upper half = y), round-to-nearest
__device__ __forceinline__ uint32_t bf16x2_hi(float x, float y) {
    uint32_t r;
    asm("cvt.rn.bf16x2.f32 %0, %1, %2;" : "=r"(r) : "f"(y), "f"(x));
    return r;
}
// residual pair: lo = f - float(bf16 hi), packed bf16x2
__device__ __forceinline__ uint32_t bf16x2_lo(float x, float y, uint32_t h) {
    float h0 = __uint_as_float(h << 16);
    float h1 = __uint_as_float(h & 0xFFFF0000u);
    return bf16x2_hi(x - h0, y - h1);
}

// ---------------- utility kernels ----------------
__global__ void zero4_kernel(float4* __restrict__ p, int n4) {
    int i = blockIdx.x * blockDim.x + threadIdx.x;
    if (i < n4) p[i] = make_float4(0.f, 0.f, 0.f, 0.f);
}

__global__ void zeroi_kernel(int* __restrict__ p, int n) {
    int i = blockIdx.x * blockDim.x + threadIdx.x;
    if (i < n) p[i] = 0;
}

__global__ void prep_weights(const float* __restrict__ att_w, const float* __restrict__ mlp_w) {
    int idx = blockIdx.x * blockDim.x + threadIdx.x;
    if (idx >= 6 * HD * HD) return;
    int w = idx >> 14;
    int k = (idx >> 7) & 127;
    int j = idx & 127;
    float val = 0.f;
    if (k < DD && j < DD) {
        const float* src = (w < 2) ? (att_w + w * DD * DD) : (mlp_w + (w - 2) * DD * DD);
        val = src[j * DD + k];
    }
    g_wt[idx] = val;
}

__global__ void prep_win(const float* __restrict__ w_in) {
    int idx = blockIdx.x * blockDim.x + threadIdx.x;
    if (idx >= IN_DIM * HD) return;
    int k = idx >> 7;
    int j = idx & 127;
    g_wtin[idx] = (j < DD) ? w_in[k * DD + j] : 0.f;
}

// bf16-split fragment weights: uint4 (b0h, b1h, b0l, b1l) per (mat, k16, tile, lane)
// b0 = k rows {2t4, 2t4+1}, b1 = k rows {8+2t4, 9+2t4} of col n = tile*8+gg.
__global__ void prep_wf() {
    int idx = blockIdx.x * blockDim.x + threadIdx.x;
    if (idx >= 6 * 8 * 16 * 32) return;
    int lane = idx & 31;
    int tile = (idx >> 5) & 15;
    int k16 = (idx >> 9) & 7;
    int mat = idx >> 12;
    int gg = lane >> 2, t4 = lane & 3;
    int k0 = k16 * 16 + 2 * t4;
    int n = tile * 8 + gg;
    const float* W = g_wt + mat * HD * HD;
    float w00 = W[k0 * HD + n],       w01 = W[(k0 + 1) * HD + n];
    float w10 = W[(k0 + 8) * HD + n], w11 = W[(k0 + 9) * HD + n];
    uint4 o;
    o.x = bf16x2_hi(w00, w01);
    o.y = bf16x2_hi(w10, w11);
    o.z = bf16x2_lo(w00, w01, o.x);
    o.w = bf16x2_lo(w10, w11, o.y);
    ((uint4*)g_wf)[idx] = o;
}

__global__ void prep_wfin() {
    int idx = blockIdx.x * blockDim.x + threadIdx.x;
    if (idx >= 13 * 16 * 32) return;
    int lane = idx & 31;
    int tile = (idx >> 5) & 15;
    int k16 = idx >> 9;                 // 0..12
    int gg = lane >> 2, t4 = lane & 3;
    int k0 = k16 * 16 + 2 * t4;
    int n = tile * 8 + gg;
    float w00 = (k0 < IN_DIM)     ? g_wtin[k0 * HD + n] : 0.f;
    float w01 = (k0 + 1 < IN_DIM) ? g_wtin[(k0 + 1) * HD + n] : 0.f;
    float w10 = (k0 + 8 < IN_DIM) ? g_wtin[(k0 + 8) * HD + n] : 0.f;
    float w11 = (k0 + 9 < IN_DIM) ? g_wtin[(k0 + 9) * HD + n] : 0.f;
    uint4 o;
    o.x = bf16x2_hi(w00, w01);
    o.y = bf16x2_hi(w10, w11);
    o.z = bf16x2_lo(w00, w01, o.x);
    o.w = bf16x2_lo(w10, w11, o.y);
    ((uint4*)g_wfin)[idx] = o;
}

// ---------------- CSR build ----------------
__global__ void hist_kernel(const int* __restrict__ ei) {
    int e = blockIdx.x * blockDim.x + threadIdx.x;
    if (e < EE) atomicAdd(&g_cnt[ei[e]], 1);
}

__global__ void scan1_kernel() {
    __shared__ int sh[256];
    int t = threadIdx.x;
    int idx = blockIdx.x * 256 + t;
    int v = (idx < NN) ? g_cnt[idx] : 0;
    sh[t] = v;
    __syncthreads();
#pragma unroll
    for (int d = 1; d < 256; d <<= 1) {
        int o = (t >= d) ? sh[t - d] : 0;
        __syncthreads();
        sh[t] += o;
        __syncthreads();
    }
    if (idx < NN) g_rowptr[idx] = sh[t] - v;
    if (t == 255) g_blksum[blockIdx.x] = sh[255];
}

__global__ void scan2_kernel(int nblk) {
    __shared__ int sh[256];
    int t = threadIdx.x;
    int v = (t < nblk) ? g_blksum[t] : 0;
    sh[t] = v;
    __syncthreads();
#pragma unroll
    for (int d = 1; d < 256; d <<= 1) {
        int o = (t >= d) ? sh[t - d] : 0;
        __syncthreads();
        sh[t] += o;
        __syncthreads();
    }
    if (t < nblk) g_blkoff[t] = sh[t] - v;
    if (t == 255) g_rowptr[NN] = sh[255];
}

__global__ void scan3_kernel() {
    int idx = blockIdx.x * 256 + threadIdx.x;
    if (idx >= NN) return;
    int r = g_rowptr[idx] + g_blkoff[blockIdx.x];
    g_rowptr[idx] = r;
    g_cur[idx] = r;
}

__global__ void scatter_kernel(const int* __restrict__ ei) {
    int e = blockIdx.x * blockDim.x + threadIdx.x;
    if (e >= EE) return;
    int s = ei[e];
    int pos = atomicAdd(&g_cur[s], 1);
    g_dstidx[pos] = ei[EE + e];
}

// ---------------- split-bf16 tensor-core GEMM (bf16x3) ----------------
// P[n][j] = sum_k U[n][k] * W[k][j] (+ bias); error ~2^-16 per product (AlBl dropped).
// Structure identical to the R8 tf32 kernel: 256 thr = 8 warps = 4 m x 2 n; tile
// 64 rows x 128 cols; warp = m16 x 8 n8-tiles; B pre-packed (one LDG.128 per
// tile: hi+lo bf16x2 fragments); A from L2; output layout unchanged.
template <int K, bool HASBIAS>
__global__ void __launch_bounds__(256) gemm_tc(const float* __restrict__ U,
                                               const uint4* __restrict__ WF,
                                               const float* __restrict__ bias,
                                               float* __restrict__ P) {
    constexpr int K16 = (K + 15) / 16;
    int tid = threadIdx.x;
    int lane = tid & 31;
    int w = tid >> 5;
    int wm = w & 3;
    int wn = w >> 2;
    int row0 = blockIdx.x * 64;
    int gg = lane >> 2, t4 = lane & 3;
    int ra = row0 + 16 * wm + gg;
    int rb = ra + 8;
    const float* A0 = U + (size_t)min(ra, NN - 1) * K;  // clamped: garbage rows never stored
    const float* A1 = U + (size_t)min(rb, NN - 1) * K;

    float acc[8][4];
#pragma unroll
    for (int t = 0; t < 8; t++) {
        acc[t][0] = 0.f; acc[t][1] = 0.f; acc[t][2] = 0.f; acc[t][3] = 0.f;
    }

    for (int k16 = 0; k16 < K16; k16++) {
        int kc = k16 * 16;
        int c0 = kc + 2 * t4;        // k cols {c0, c0+1}
        int c1 = kc + 8 + 2 * t4;    // k cols {c1, c1+1}
        float2 fa0, fa1, fa2, fa3;
        if (K % 16 != 0 && k16 == K16 - 1) {
            // tail: per-element guards (input GEMM only)
            fa0.x = (c0 < K) ? A0[c0] : 0.f;     fa0.y = (c0 + 1 < K) ? A0[c0 + 1] : 0.f;
            fa1.x = (c0 < K) ? A1[c0] : 0.f;     fa1.y = (c0 + 1 < K) ? A1[c0 + 1] : 0.f;
            fa2.x = (c1 < K) ? A0[c1] : 0.f;     fa2.y = (c1 + 1 < K) ? A0[c1 + 1] : 0.f;
            fa3.x = (c1 < K) ? A1[c1] : 0.f;     fa3.y = (c1 + 1 < K) ? A1[c1 + 1] : 0.f;
        } else {
            fa0 = *(const float2*)&A0[c0];
            fa1 = *(const float2*)&A1[c0];
            fa2 = *(const float2*)&A0[c1];
            fa3 = *(const float2*)&A1[c1];
        }
        uint32_t h0 = bf16x2_hi(fa0.x, fa0.y), h1 = bf16x2_hi(fa1.x, fa1.y);
        uint32_t h2 = bf16x2_hi(fa2.x, fa2.y), h3 = bf16x2_hi(fa3.x, fa3.y);
        uint32_t l0 = bf16x2_lo(fa0.x, fa0.y, h0), l1 = bf16x2_lo(fa1.x, fa1.y, h1);
        uint32_t l2 = bf16x2_lo(fa2.x, fa2.y, h2), l3 = bf16x2_lo(fa3.x, fa3.y, h3);
        const uint4* wf = WF + ((size_t)k16 * 16 + wn * 8) * 32 + lane;
#pragma unroll
        for (int t = 0; t < 8; t++) {
            uint4 bv = wf[t * 32];   // (b0h, b1h, b0l, b1l)
            mma_bf16(acc[t], h0, h1, h2, h3, bv.x, bv.y);  // hi*hi
            mma_bf16(acc[t], h0, h1, h2, h3, bv.z, bv.w);  // hi*lo
            mma_bf16(acc[t], l0, l1, l2, l3, bv.x, bv.y);  // lo*hi
        }
    }

#pragma unroll
    for (int t = 0; t < 8; t++) {
        int j0 = 64 * wn + 8 * t + 2 * t4;   // even, 0..126
        float b0 = 0.f, b1 = 0.f;
        if (HASBIAS) {
            b0 = bias[j0];                       // j0 <= 126 < DD always
            b1 = (j0 + 1 < DD) ? bias[j0 + 1] : 0.f;
        }
        float d0 = acc[t][0] + b0, d1 = acc[t][1] + b1;
        float d2 = acc[t][2] + b0, d3 = acc[t][3] + b1;
        if (j0 + 1 == 127) { d1 = 0.f; d3 = 0.f; }  // padding col
        if (ra < NN) *(float2*)&P[(size_t)ra * HD + j0] = make_float2(d0, d1);
        if (rb < NN) *(float2*)&P[(size_t)rb * HD + j0] = make_float2(d2, d3);
    }
}

// ---------------- warp-per-node elementwise kernels (unchanged) ----------------

__device__ __forceinline__ float4 logmap_quad(float4 o, float ss, float x0,
                                              float c, float sc, int lane) {
    float yn = fmaxf(sqrtf(ss), 1e-9f);
    float d = sc * acoshf(fmaxf(x0 / sc, 1.f + EPSF));
    float a = d / yn;
    float nx = __shfl_down_sync(0xffffffffu, o.x, 1);
    float4 u;
    u.x = a * o.y; u.y = a * o.z; u.z = a * o.w;
    u.w = (lane == 31) ? 0.f : a * nx;
    return u;
}

__global__ void expmap_kernel(const float* __restrict__ P, float* __restrict__ out,
                              const float* __restrict__ cptr) {
    int warp = (blockIdx.x * blockDim.x + threadIdx.x) >> 5;
    int lane = threadIdx.x & 31;
    if (warp >= NN) return;
    float c = cptr[0], sc = sqrtf(c);
    float4 v = ((const float4*)(P + (size_t)warp * HD))[lane];
    float s = warp_sum(v.x * v.x + v.y * v.y + v.z * v.z + v.w * v.w);
    float n = fmaxf(sqrtf(s), 1e-9f);
    float sh = sc * sinhf(n / sc) / n;
    float wprev = __shfl_up_sync(0xffffffffu, v.w, 1);
    float4 o;
    o.x = (lane == 0) ? 0.f : sh * wprev;
    o.y = sh * v.x; o.z = sh * v.y; o.w = sh * v.z;
    float ss = warp_sum(((lane == 0) ? 0.f : o.x * o.x) + o.y * o.y + o.z * o.z + o.w * o.w);
    if (lane == 0) o.x = sqrtf(c + ss);
    ((float4*)(out + (size_t)warp * HD))[lane] = o;
}

__global__ void expmap_u_kernel(const float* __restrict__ P, float* __restrict__ H,
                                float* __restrict__ U, const float* __restrict__ cptr) {
    int warp = (blockIdx.x * blockDim.x + threadIdx.x) >> 5;
    int lane = threadIdx.x & 31;
    if (warp >= NN) return;
    float c = cptr[0], sc = sqrtf(c);
    float4 v = ((const float4*)(P + (size_t)warp * HD))[lane];
    float s = warp_sum(v.x * v.x + v.y * v.y + v.z * v.z + v.w * v.w);
    float n = fmaxf(sqrtf(s), 1e-9f);
    float sh = sc * sinhf(n / sc) / n;
    float wprev = __shfl_up_sync(0xffffffffu, v.w, 1);
    float4 o;
    o.x = (lane == 0) ? 0.f : sh * wprev;
    o.y = sh * v.x; o.z = sh * v.y; o.w = sh * v.z;
    float ss = warp_sum(((lane == 0) ? 0.f : o.x * o.x) + o.y * o.y + o.z * o.z + o.w * o.w);
    float x0 = sqrtf(c + ss);
    if (lane == 0) o.x = x0;
    ((float4*)(H + (size_t)warp * HD))[lane] = o;
    ((float4*)(U + (size_t)warp * HD))[lane] = logmap_quad(o, ss, x0, c, sc, lane);
}

__global__ void agg_combine_kernel(const float* __restrict__ hl, const float* __restrict__ h,
                                   float* __restrict__ U, const float* __restrict__ cptr,
                                   const float* __restrict__ epsp, int l) {
    int warp = (blockIdx.x * blockDim.x + threadIdx.x) >> 5;
    int lane = threadIdx.x & 31;
    if (warp >= NN) return;
    float c = cptr[0], sc = sqrtf(c), ep = epsp[l];
    bool c1 = (sc == 1.f);
    int beg = g_rowptr[warp], end = g_rowptr[warp + 1];
    float4 a = ((const float4*)(hl + (size_t)warp * HD))[lane];
    float ax0 = (lane == 0) ? -a.x : a.x;
    float4 mv = make_float4(0.f, 0.f, 0.f, 0.f);
    int d = (beg < end) ? g_dstidx[beg] : 0;
    for (int e = beg; e < end; e++) {
        int dn = (e + 1 < end) ? g_dstidx[e + 1] : 0;
        float4 b = ((const float4*)(hl + (size_t)d * HD))[lane];
        float4 hv = ((const float4*)(h + (size_t)d * HD))[lane];
        float p = ax0 * b.x + a.y * b.y + a.z * b.z + a.w * b.w;
        p = warp_sum(p);
        float val = fmaxf(-p / c, 1.f + EPSF);
        float att = c1 ? (1.f / (val + sqrtf(val * val - 1.f)))
                       : expf(-sc * acoshf(val));
        mv.x = fmaf(att, hv.x, mv.x);
        mv.y = fmaf(att, hv.y, mv.y);
        mv.z = fmaf(att, hv.z, mv.z);
        mv.w = fmaf(att, hv.w, mv.w);
        d = dn;
    }
    float4 hv = ((const float4*)(h + (size_t)warp * HD))[lane];
    float m0 = __shfl_sync(0xffffffffu, mv.x, 0);
    float pm = warp_sum(((lane == 0) ? 0.f : mv.x * mv.x) + mv.y * mv.y + mv.z * mv.z + mv.w * mv.w);
    float denom = sqrtf(fmaxf(m0 * m0 - pm, 1e-9f));
    float r = sc / denom;
    float axx = r * mv.x, ay = r * mv.y, az = r * mv.z, aw = r * mv.w;
    float ssum = warp_sum(((lane == 0) ? 0.f : axx * axx) + ay * ay + az * az + aw * aw);
    float t = sqrtf(c + ssum);
    float yn_a = fmaxf(sqrtf(ssum), 1e-9f);
    float d1 = sc * acoshf(fmaxf(t / sc, 1.f + EPSF));
    float cA = d1 / yn_a;
    float ph = warp_sum(((lane == 0) ? 0.f : hv.x * hv.x) + hv.y * hv.y + hv.z * hv.z + hv.w * hv.w);
    float hp0 = sqrtf(c + ph);
    float yn_h = fmaxf(sqrtf(ph), 1e-9f);
    float d2 = sc * acoshf(fmaxf(hp0 / sc, 1.f + EPSF));
    float cH = (1.f + ep) * d2 / yn_h;
    float4 vv;
    vv.x = (lane == 0) ? 0.f : cA * axx + cH * hv.x;
    vv.y = cA * ay + cH * hv.y;
    vv.z = cA * az + cH * hv.z;
    vv.w = cA * aw + cH * hv.w;
    float pv = warp_sum(vv.x * vv.x + vv.y * vv.y + vv.z * vv.z + vv.w * vv.w);
    float n = fmaxf(sqrtf(pv), 1e-9f);
    float sh = sc * sinhf(n / sc) / n;
    float4 o;
    o.x = (lane == 0) ? 0.f : sh * vv.x;
    o.y = sh * vv.y; o.z = sh * vv.z; o.w = sh * vv.w;
    float so = warp_sum(((lane == 0) ? 0.f : o.x * o.x) + o.y * o.y + o.z * o.z + o.w * o.w);
    float x0 = sqrtf(c + so);
    if (lane == 0) o.x = x0;
    ((float4*)(U + (size_t)warp * HD))[lane] = logmap_quad(o, so, x0, c, sc, lane);
}

template <bool WRITE_H, bool POOL>
__global__ void mlp_epi_kernel(const float* __restrict__ P, float* __restrict__ H,
                               float* __restrict__ U, const float* __restrict__ cptr,
                               const int* __restrict__ batch, float* __restrict__ out,
                               int loff) {
    int warp = (blockIdx.x * blockDim.x + threadIdx.x) >> 5;
    int lane = threadIdx.x & 31;
    if (warp >= NN) return;
    float c = cptr[0], sc = sqrtf(c);
    float4 v = ((const float4*)(P + (size_t)warp * HD))[lane];
    float s = warp_sum(v.x * v.x + v.y * v.y + v.z * v.z + v.w * v.w);
    float n1 = fmaxf(sqrtf(s), 1e-9f);
    float sh1 = sc * sinhf(n1 / sc) / n1;
    float sx = sh1 * v.x, sy = sh1 * v.y, sz = sh1 * v.z, sw = sh1 * v.w;
    float ssum = warp_sum(sx * sx + sy * sy + sz * sz + sw * sw);
    float x0p = sqrtf(c + ssum);
    float ynp = fmaxf(sqrtf(ssum), 1e-9f);
    float dp = sc * acoshf(fmaxf(x0p / sc, 1.f + EPSF));
    float cf = dp / ynp;
    float tx = tanhf(cf * sx), ty = tanhf(cf * sy), tz = tanhf(cf * sz), tw = tanhf(cf * sw);
    float s2 = warp_sum(tx * tx + ty * ty + tz * tz + tw * tw);
    float n2 = fmaxf(sqrtf(s2), 1e-9f);
    float sh2 = sc * sinhf(n2 / sc) / n2;
    float wprev = __shfl_up_sync(0xffffffffu, tw, 1);
    float x0 = sc * coshf(n2 / sc);
    float4 o;
    o.x = (lane == 0) ? x0 : sh2 * wprev;
    o.y = sh2 * tx; o.z = sh2 * ty; o.w = sh2 * tz;
    if (WRITE_H) ((float4*)(H + (size_t)warp * HD))[lane] = o;
    float sl = warp_sum(((lane == 0) ? 0.f : o.x * o.x) + o.y * o.y + o.z * o.z + o.w * o.w);
    float yn = fmaxf(sqrtf(sl), 1e-9f);
    float d = sc * acoshf(fmaxf(x0 / sc, 1.f + EPSF));
    float a = d / yn;
    float nx = __shfl_down_sync(0xffffffffu, o.x, 1);
    float4 u;
    u.x = a * o.y; u.y = a * o.z; u.z = a * o.w;
    u.w = (lane == 31) ? 0.f : a * nx;
    ((float4*)(U + (size_t)warp * HD))[lane] = u;
    if (POOL) {
        int g = batch[warp];
        red_v4(out + (size_t)g * (2 * HD) + loff + lane * 4,
               (lane == 0) ? 0.f : a * o.x, a * o.y, a * o.z, a * o.w);
    }
}

// ---------------- host launcher ----------------
extern "C" void kernel_launch(void* const* d_in, const int* in_sizes, int n_in,
                              void* d_out, int out_size) {
    (void)in_sizes; (void)n_in; (void)out_size;
    const float* x     = (const float*)d_in[0];
    const float* c     = (const float*)d_in[1];
    const float* w_in  = (const float*)d_in[2];
    const float* att_w = (const float*)d_in[3];
    const float* att_b = (const float*)d_in[4];
    const float* eps   = (const float*)d_in[5];
    const float* mlp_w = (const float*)d_in[6];
    const float* mlp_b = (const float*)d_in[7];
    const int*   ei    = (const int*)d_in[8];
    const int*   batch = (const int*)d_in[9];
    float* out = (float*)d_out;

    float *ph, *pu, *pp, *phl, *pwf, *pwfin;
    int* pcnt;
    cudaGetSymbolAddress((void**)&ph, g_h);
    cudaGetSymbolAddress((void**)&pu, g_u);
    cudaGetSymbolAddress((void**)&pp, g_p);
    cudaGetSymbolAddress((void**)&phl, g_hl);
    cudaGetSymbolAddress((void**)&pwf, g_wf);
    cudaGetSymbolAddress((void**)&pwfin, g_wfin);
    cudaGetSymbolAddress((void**)&pcnt, g_cnt);

    const int NB = (NN + 7) / 8;        // warp-per-node blocks
    const int TB = (NN + 63) / 64;      // tensor GEMM blocks (64 rows each)
    const int SCB = (NN + 255) / 256;   // scan blocks

    zero4_kernel<<<(GG * 2 * HD / 4 + 255) / 256, 256>>>((float4*)out, GG * 2 * HD / 4);
    prep_weights<<<(6 * HD * HD + 255) / 256, 256>>>(att_w, mlp_w);
    prep_win<<<(IN_DIM * HD + 255) / 256, 256>>>(w_in);
    prep_wf<<<(6 * 8 * 16 * 32 + 255) / 256, 256>>>();
    prep_wfin<<<(13 * 16 * 32 + 255) / 256, 256>>>();

    // CSR build (once; reused by both layers)
    zeroi_kernel<<<SCB, 256>>>(pcnt, NN);
    hist_kernel<<<(EE + 255) / 256, 256>>>(ei);
    scan1_kernel<<<SCB, 256>>>();
    scan2_kernel<<<1, 256>>>(SCB);
    scan3_kernel<<<SCB, 256>>>();
    scatter_kernel<<<(EE + 255) / 256, 256>>>(ei);

    // input: h0 = proj(expmap0([0, x @ w_in])), u0 = logmap0(h0)
    gemm_tc<IN_DIM, false><<<TB, 256>>>(x, (const uint4*)pwfin, nullptr, pp);
    expmap_u_kernel<<<NB, 256>>>(pp, ph, pu, c);

    for (int l = 0; l < 2; l++) {
        // attention linear: hl = proj(expmap0(u @ W + b))
        gemm_tc<HD, true><<<TB, 256>>>(pu, (const uint4*)(pwf + (size_t)l * 8 * 16 * 32 * 4),
                                       att_b + l * DD, pp);
        expmap_kernel<<<NB, 256>>>(pp, phl, c);
        // centroid + GIN combine -> u
        agg_combine_kernel<<<NB, 256>>>(phl, ph, pu, c, eps, l);
        // MLP 0
        gemm_tc<HD, true><<<TB, 256>>>(pu, (const uint4*)(pwf + (size_t)(2 + l * 2 + 0) * 8 * 16 * 32 * 4),
                                       mlp_b + (l * 2 + 0) * DD, pp);
        mlp_epi_kernel<false, false><<<NB, 256>>>(pp, nullptr, pu, c, nullptr, nullptr, 0);
        // MLP 1 (+ layer output + pooled readout)
        gemm_tc<HD, true><<<TB, 256>>>(pu, (const uint4*)(pwf + (size_t)(2 + l * 2 + 1) * 8 * 16 * 32 * 4),
                                       mlp_b + (l * 2 + 1) * DD, pp);
        mlp_epi_kernel<true, true><<<NB, 256>>>(pp, ph, pu, c, batch, out, l * HD);
    }
}